// round 17
// baseline (speedup 1.0000x reference)
#include <cuda_runtime.h>
#include <cuda_fp16.h>
#include <math.h>
#include <stdint.h>

#define BATCH   16384
#define D_IN    128
#define HID     16
#define N_INNER 255
#define N_LEAF  256
#define DEPTH   8

#define NCOLS   4096
#define MT      128
#define NTILE   128
#define NT      32
#define GT      512

// ---------------- scratch ----------------
__device__ __half g_wh[NCOLS * D_IN];

// ---------------- PTX helpers ----------------
#define CP16(dst, src) \
    asm volatile("cp.async.cg.shared.global [%0], [%1], 16;" :: "r"(dst), "l"(src))
#define CP_COMMIT() asm volatile("cp.async.commit_group;" ::: "memory")
#define CP_WAIT0()  asm volatile("cp.async.wait_group 0;" ::: "memory")

#define LDSM4(R, addr) \
    asm volatile("ldmatrix.sync.aligned.m8n8.x4.shared.b16 {%0,%1,%2,%3}, [%4];" \
                 : "=r"((R)[0]), "=r"((R)[1]), "=r"((R)[2]), "=r"((R)[3]) : "r"(addr))

#define MMA16816(C, A, B0, B1) \
    asm volatile("mma.sync.aligned.m16n8k16.row.col.f32.f16.f16.f32 " \
                 "{%0,%1,%2,%3}, {%4,%5,%6,%7}, {%8,%9}, {%0,%1,%2,%3};" \
                 : "+f"((C)[0]), "+f"((C)[1]), "+f"((C)[2]), "+f"((C)[3]) \
                 : "r"((A)[0]), "r"((A)[1]), "r"((A)[2]), "r"((A)[3]), \
                   "r"(B0), "r"(B1))

// XOR swizzle for 256 B rows, 16B chunks
__device__ __forceinline__ uint32_t sw_off(int r, int j) {
    return (uint32_t)(r * 256 + (((j & 8) | ((j ^ r) & 7)) << 4));
}

__device__ __forceinline__ uint32_t pack_h2(float lo, float hi) {
    __half2 h = __floats2half2_rn(lo, hi);
    return *(uint32_t*)&h;
}

// ---------------- prep kernel (W only; x converted in-register in main kernel) -----
__global__ void cvt_w_kernel(const float* __restrict__ W1) {
    __shared__ float s[128 * 17 + 16];
    const int n   = blockIdx.x;
    const int tid = threadIdx.x;
    if (n < N_INNER) {
        for (int t = tid; t < 2048; t += 256) {
            int k = t >> 4, h = t & 15;
            s[k * 17 + h] = W1[n * 2048 + t];
        }
        __syncthreads();
        for (int t = tid; t < 2048; t += 256) {
            int h = t >> 7, k = t & 127;
            g_wh[(n * HID + h) * D_IN + k] = __float2half(s[k * 17 + h]);
        }
    } else {
        for (int t = tid; t < 2048; t += 256)
            g_wh[n * HID * D_IN + t] = __float2half(0.f);
    }
}

// ---------------- SMEM layout: 196 KB, 1 CTA/SM ----------------
// B 2 bufs x 32KB @0 ; pbuf [128][257] f32 @65536
#define SM_B   0
#define SM_P   65536
#define PSTR   257
#define SMEM_TOTAL (65536 + 131584)

__device__ __forceinline__ void load_tile(uint32_t dst, const __half* src, int tid) {
    #pragma unroll
    for (int it = 0; it < 4; it++) {
        int c = tid + it * GT;
        int r = c >> 4, j = c & 15;
        CP16(dst + sw_off(r, j), src + r * D_IN + j * 8);
    }
}

__global__ __launch_bounds__(GT, 1)
void gemm_tree_kernel(const float* __restrict__ x,
                      const float* __restrict__ b1, const float* __restrict__ W2,
                      const float* __restrict__ b2, const float* __restrict__ leaf,
                      float* __restrict__ out)
{
    extern __shared__ char smem[];
    uint32_t sb = (uint32_t)__cvta_generic_to_shared(smem);
    float* pbuf = (float*)(smem + SM_P);

    const int tid    = threadIdx.x;
    const int lane   = tid & 31;
    const int wid    = tid >> 5;
    const int warp_m = wid & 3;
    const int warp_n = wid >> 2;
    const int row0   = blockIdx.x * MT;

    // B tile 0 into buf0
    load_tile(sb + SM_B, g_wh, tid);
    CP_COMMIT();

    // ---- A fragments: load x (f32) directly into mma fragment registers ----
    // m16n8k16 A layout: reg0 (r=lane>>2, c=(lane&3)*2), reg1 r+8, reg2 c+8, reg3 r+8,c+8
    uint32_t a_reg[8][2][4];
    {
        const float* xr = x + (size_t)(row0 + warp_m * 32 + (lane >> 2)) * D_IN
                            + (lane & 3) * 2;
        #pragma unroll
        for (int ks = 0; ks < 8; ks++) {
            #pragma unroll
            for (int mf = 0; mf < 2; mf++) {
                const float* base = xr + mf * 16 * D_IN + ks * 16;
                float2 v0 = *(const float2*)(base);
                float2 v1 = *(const float2*)(base + 8 * D_IN);
                float2 v2 = *(const float2*)(base + 8);
                float2 v3 = *(const float2*)(base + 8 * D_IN + 8);
                a_reg[ks][mf][0] = pack_h2(v0.x, v0.y);
                a_reg[ks][mf][1] = pack_h2(v1.x, v1.y);
                a_reg[ks][mf][2] = pack_h2(v2.x, v2.y);
                a_reg[ks][mf][3] = pack_h2(v3.x, v3.y);
            }
        }
    }

    const int rb_base = warp_n * 32 + (lane & 7) + ((lane >> 4) & 1) * 8;  // + bf*16
    const int jb_add  = (lane >> 3) & 1;
    const int q = lane >> 2, g = lane & 3;

    float* outp = out + (size_t)BATCH * 257;

    for (int nt = 0; nt < NT; nt++) {
        const int s = nt & 1;

        CP_WAIT0();
        __syncthreads();   // B[s] ready; previous pbuf reads done

        if (nt + 1 < NT) {
            load_tile(sb + SM_B + (uint32_t)(1 - s) * 32768u,
                      g_wh + (size_t)(nt + 1) * NTILE * D_IN, tid);
            CP_COMMIT();
        }

        float c[8][4];
        #pragma unroll
        for (int f = 0; f < 8; f++)
            #pragma unroll
            for (int e = 0; e < 4; e++) c[f][e] = 0.f;

        const uint32_t bB = sb + SM_B + (uint32_t)s * 32768u;

        #pragma unroll
        for (int ks = 0; ks < 8; ks++) {
            const int j0 = ks * 2;
            uint32_t bh[2][4];
            LDSM4(bh[0], bB + sw_off(rb_base,      j0 + jb_add));
            LDSM4(bh[1], bB + sw_off(rb_base + 16, j0 + jb_add));
            #pragma unroll
            for (int mf = 0; mf < 2; mf++)
                #pragma unroll
                for (int bf = 0; bf < 2; bf++)
                    #pragma unroll
                    for (int h = 0; h < 2; h++)
                        MMA16816(c[mf * 4 + bf * 2 + h], a_reg[ks][mf],
                                 bh[bf][2 * h], bh[bf][2 * h + 1]);
        }

        // ---- epilogue: +b1, relu, dot W2, +b2, sigmoid -> pbuf ----
        #pragma unroll
        for (int m = 0; m < 2; m++) {
            #pragma unroll
            for (int nd = 0; nd < 2; nd++) {
                float s0 = 0.f, s1 = 0.f;
                #pragma unroll
                for (int h = 0; h < 2; h++) {
                    int f = m * 4 + nd * 2 + h;
                    int gcol = nt * 128 + warp_n * 32 + (nd * 2 + h) * 8 + 2 * g;
                    float bb0 = 0.f, ww0 = 0.f, bb1 = 0.f, ww1 = 0.f;
                    if (gcol < N_INNER * HID) {
                        bb0 = __ldg(b1 + gcol);     ww0 = __ldg(W2 + gcol);
                        bb1 = __ldg(b1 + gcol + 1); ww1 = __ldg(W2 + gcol + 1);
                    }
                    s0 += fmaxf(c[f][0] + bb0, 0.f) * ww0 + fmaxf(c[f][1] + bb1, 0.f) * ww1;
                    s1 += fmaxf(c[f][2] + bb0, 0.f) * ww0 + fmaxf(c[f][3] + bb1, 0.f) * ww1;
                }
                s0 += __shfl_xor_sync(0xffffffffu, s0, 1);
                s0 += __shfl_xor_sync(0xffffffffu, s0, 2);
                s1 += __shfl_xor_sync(0xffffffffu, s1, 1);
                s1 += __shfl_xor_sync(0xffffffffu, s1, 2);
                if (g == nd) {
                    int nl = warp_n * 2 + nd;
                    int ng = nt * 8 + nl;
                    float b2v = (ng < N_INNER) ? __ldg(b2 + ng) : 0.f;
                    int r0 = warp_m * 32 + m * 16 + q;
                    pbuf[r0 * PSTR + ng]       = 1.f / (1.f + __expf(-(s0 + b2v)));
                    pbuf[(r0 + 8) * PSTR + ng] = 1.f / (1.f + __expf(-(s1 + b2v)));
                }
            }
        }
        __syncthreads();

        // coalesced p write
        #pragma unroll
        for (int i2 = 0; i2 < 2; i2++) {
            int i = tid + i2 * GT;
            int r = i >> 3, cl = i & 7;
            int ng = nt * 8 + cl;
            if (ng < N_INNER)
                outp[(size_t)(row0 + r) * N_INNER + ng] = pbuf[r * PSTR + ng];
        }
    }

    // ================= fused tree pass =================
    __syncthreads();

    const float4* lf4 = (const float4*)(leaf + 8 * lane);
    const float4 l0 = lf4[0], l1 = lf4[1];

    #pragma unroll 1
    for (int rr = 0; rr < 8; rr++) {
        const int r   = wid * 8 + rr;
        const int row = row0 + r;
        const float* prow = pbuf + r * PSTR;
        float* nr = out + (size_t)BATCH * 512 + (size_t)row * N_INNER;
        float* pp = out + (size_t)BATCH + (size_t)row * N_LEAF;

        float pl[5];
        #pragma unroll
        for (int l = 0; l < 5; l++) {
            const int sz = 1 << l;
            pl[l] = (lane < sz) ? prow[sz - 1 + lane] : 0.f;
        }
        float p5  = prow[31 + lane];
        float p6a = prow[63 + 2 * lane];
        float p6b = prow[63 + 2 * lane + 1];
        float p7[4];
        #pragma unroll
        for (int j = 0; j < 4; j++) p7[j] = prow[127 + 4 * lane + j];

        float rv = (lane == 0) ? 1.f : 0.f;
        #pragma unroll
        for (int l = 0; l < 5; l++) {
            const int sz = 1 << l;
            if (lane < sz) nr[sz - 1 + lane] = rv;
            float rp = __shfl_sync(0xffffffffu, rv, lane >> 1);
            float pq = __shfl_sync(0xffffffffu, pl[l], lane >> 1);
            rv = (lane & 1) ? rp * pq : rp * (1.f - pq);
        }

        nr[31 + lane] = rv;
        float r6a = rv * (1.f - p5);
        float r6b = rv * p5;

        nr[63 + 2 * lane]     = r6a;
        nr[63 + 2 * lane + 1] = r6b;
        float r7[4] = { r6a * (1.f - p6a), r6a * p6a, r6b * (1.f - p6b), r6b * p6b };

        #pragma unroll
        for (int j = 0; j < 4; j++) nr[127 + 4 * lane + j] = r7[j];

        float r8[8];
        #pragma unroll
        for (int j = 0; j < 4; j++) {
            r8[2 * j]     = r7[j] * (1.f - p7[j]);
            r8[2 * j + 1] = r7[j] * p7[j];
        }
        float4* pp4 = (float4*)(pp + 8 * lane);
        pp4[0] = make_float4(r8[0], r8[1], r8[2], r8[3]);
        pp4[1] = make_float4(r8[4], r8[5], r8[6], r8[7]);

        float hs = r8[0] * l0.x + r8[1] * l0.y + r8[2] * l0.z + r8[3] * l0.w
                 + r8[4] * l1.x + r8[5] * l1.y + r8[6] * l1.z + r8[7] * l1.w;
        #pragma unroll
        for (int o = 16; o; o >>= 1) hs += __shfl_down_sync(0xffffffffu, hs, o);
        if (lane == 0) out[row] = hs;
    }
}

// ---------------- launch ----------------
extern "C" void kernel_launch(void* const* d_in, const int* in_sizes, int n_in,
                              void* d_out, int out_size)
{
    const float* x    = (const float*)d_in[0];
    const float* W1   = (const float*)d_in[1];
    const float* b1   = (const float*)d_in[2];
    const float* W2   = (const float*)d_in[3];
    const float* b2   = (const float*)d_in[4];
    const float* leaf = (const float*)d_in[5];
    float* out = (float*)d_out;

    cvt_w_kernel<<<256, 256>>>(W1);

    cudaFuncSetAttribute(gemm_tree_kernel, cudaFuncAttributeMaxDynamicSharedMemorySize, SMEM_TOTAL);
    gemm_tree_kernel<<<BATCH / MT, GT, SMEM_TOTAL>>>(x, b1, W2, b2, leaf, out);
}